// round 1
// baseline (speedup 1.0000x reference)
#include <cuda_runtime.h>
#include <cstdint>
#include <math.h>

#define BATCH 8
#define CH 1024
#define SEQ 1024
#define HEADS 16
#define DHEAD 64
#define GROUPS 32
#define CPG (CH / GROUPS)
#define LAYERS 6
#define SPECD 80

// Scratch buffers (allowed: __device__ globals, no runtime allocation)
__device__ float g_x[BATCH * CH * SEQ];        // residual stream
__device__ float g_h[BATCH * CH * SEQ];        // groupnorm output
__device__ float g_qkv[BATCH * 3 * CH * SEQ];  // qkv activations
__device__ float g_ao[BATCH * CH * SEQ];       // attention output

// ---------------------------------------------------------------------------
// Generic batched GEMM: out[b,m,n] = bias[m] + (res? res[b,m,n]:0)
//                                    + sum_k W[m,k] * X[b,k,n]
// W: M x K row-major (shared across batch). X: per-batch K x N row-major.
// Tiles: 64x64x16, 256 threads, 4x4 micro-tile per thread.
// ---------------------------------------------------------------------------
__global__ __launch_bounds__(256) void gemm_bias_res(
    const float* __restrict__ W, const float* __restrict__ X,
    const float* __restrict__ bias, const float* __restrict__ res,
    float* __restrict__ out, int M, int N, int K)
{
    __shared__ __align__(16) float As[16][64];
    __shared__ __align__(16) float Bs[16][64];

    const int b  = blockIdx.z;
    const int m0 = blockIdx.y * 64;
    const int n0 = blockIdx.x * 64;
    const float* Xb = X + (size_t)b * K * N;

    const int tid  = threadIdx.x;
    const int tm   = tid >> 4;          // 0..15
    const int tn   = tid & 15;          // 0..15
    const int la_m = tid >> 2;          // 0..63
    const int la_k = (tid & 3) * 4;     // 0,4,8,12
    const int lb_k = tid >> 4;          // 0..15
    const int lb_n = (tid & 15) * 4;    // 0..60

    float acc[4][4] = {};

    for (int k0 = 0; k0 < K; k0 += 16) {
        float4 av = *(const float4*)(W + (size_t)(m0 + la_m) * K + k0 + la_k);
        As[la_k + 0][la_m] = av.x;
        As[la_k + 1][la_m] = av.y;
        As[la_k + 2][la_m] = av.z;
        As[la_k + 3][la_m] = av.w;
        *(float4*)&Bs[lb_k][lb_n] =
            *(const float4*)(Xb + (size_t)(k0 + lb_k) * N + n0 + lb_n);
        __syncthreads();
#pragma unroll
        for (int kk = 0; kk < 16; kk++) {
            float4 a  = *(float4*)&As[kk][tm * 4];
            float4 bv = *(float4*)&Bs[kk][tn * 4];
            acc[0][0] += a.x * bv.x; acc[0][1] += a.x * bv.y;
            acc[0][2] += a.x * bv.z; acc[0][3] += a.x * bv.w;
            acc[1][0] += a.y * bv.x; acc[1][1] += a.y * bv.y;
            acc[1][2] += a.y * bv.z; acc[1][3] += a.y * bv.w;
            acc[2][0] += a.z * bv.x; acc[2][1] += a.z * bv.y;
            acc[2][2] += a.z * bv.z; acc[2][3] += a.z * bv.w;
            acc[3][0] += a.w * bv.x; acc[3][1] += a.w * bv.y;
            acc[3][2] += a.w * bv.z; acc[3][3] += a.w * bv.w;
        }
        __syncthreads();
    }

    const size_t ob = (size_t)b * M * N;
#pragma unroll
    for (int i = 0; i < 4; i++) {
        const int m = m0 + tm * 4 + i;
        const float bi = bias[m];
#pragma unroll
        for (int j = 0; j < 4; j++) {
            const int n = n0 + tn * 4 + j;
            float v = acc[i][j] + bi;
            const size_t o = ob + (size_t)m * N + n;
            if (res) v += res[o];
            out[o] = v;
        }
    }
}

// ---------------------------------------------------------------------------
// GroupNorm: one block per (batch, group). Group = 32 channels x 1024 = 32768.
// ---------------------------------------------------------------------------
__global__ __launch_bounds__(256) void groupnorm(
    const float* __restrict__ x, const float* __restrict__ w,
    const float* __restrict__ bb, float* __restrict__ h)
{
    const int bg = blockIdx.x;
    const int b  = bg >> 5;
    const int g  = bg & 31;
    const size_t off = (size_t)b * CH * SEQ + (size_t)g * CPG * SEQ;
    const float* xp = x + off;
    float* hp = h + off;
    const int n = CPG * SEQ;  // 32768

    float s = 0.f, s2 = 0.f;
    for (int i = threadIdx.x; i < n; i += 256) {
        float v = xp[i];
        s += v; s2 += v * v;
    }
#pragma unroll
    for (int o = 16; o; o >>= 1) {
        s  += __shfl_xor_sync(0xffffffffu, s,  o);
        s2 += __shfl_xor_sync(0xffffffffu, s2, o);
    }
    __shared__ float ws[8], ws2[8];
    const int wi = threadIdx.x >> 5, li = threadIdx.x & 31;
    if (li == 0) { ws[wi] = s; ws2[wi] = s2; }
    __syncthreads();
    if (threadIdx.x == 0) {
        float S = 0.f, S2 = 0.f;
#pragma unroll
        for (int k = 0; k < 8; k++) { S += ws[k]; S2 += ws2[k]; }
        const float mean = S / n;
        const float var  = S2 / n - mean * mean;
        ws[0]  = mean;
        ws2[0] = rsqrtf(var + 1e-5f);
    }
    __syncthreads();
    const float mean = ws[0], rstd = ws2[0];
    for (int i = threadIdx.x; i < n; i += 256) {
        const int c = g * CPG + (i >> 10);
        hp[i] = (xp[i] - mean) * rstd * w[c] + bb[c];
    }
}

// ---------------------------------------------------------------------------
// Fused attention, flash-style. One block = (b,h) x 64-query tile.
// qkv layout: [B, 3*CH, SEQ]; head h owns rows [h*192, h*192+192):
//   q rows [0,64), k rows [64,128), v rows [128,192) within the head slice.
// S[t,s] = 0.125 * sum_c q[c,t] k[c,s]; online softmax over s;
// O[t,c] = sum_s P[t,s] v[c,s]; output to ao[b, h*64+c, t].
// Shared: Qs[64][64], KP[64][64] (K then reused for P), Vt[64][65] (V^T, padded)
// ---------------------------------------------------------------------------
__global__ __launch_bounds__(256) void attn(
    const float* __restrict__ qkv, float* __restrict__ ao)
{
    extern __shared__ float sm[];
    float* Qs = sm;                 // 64*64
    float* KP = sm + 64 * 64;       // 64*64
    float* Vt = sm + 2 * 64 * 64;   // 64*65 (Vt[s*65 + c])

    const int bh = blockIdx.y;
    const int b  = bh >> 4;
    const int hh = bh & 15;
    const int t0 = blockIdx.x * 64;
    const float* base = qkv + ((size_t)b * 3 * CH + (size_t)hh * 192) * SEQ;

    const int tid = threadIdx.x;
    const int ty = tid >> 4, tx = tid & 15;
    const int t4 = ty * 4, c4 = tx * 4;

    // Load Q tile: Qs[c][t]
    for (int idx = tid; idx < 64 * 64; idx += 256) {
        const int c = idx >> 6, t = idx & 63;
        Qs[c * 64 + t] = base[(size_t)c * SEQ + t0 + t];
    }

    float m_run[4], l_run[4], O[4][4];
#pragma unroll
    for (int i = 0; i < 4; i++) {
        m_run[i] = -1e30f; l_run[i] = 0.f;
#pragma unroll
        for (int j = 0; j < 4; j++) O[i][j] = 0.f;
    }

    for (int st = 0; st < SEQ / 64; st++) {
        const int s0 = st * 64;
        __syncthreads();  // prev PV reads done
        for (int idx = tid; idx < 64 * 64; idx += 256) {
            const int c = idx >> 6, s = idx & 63;
            KP[c * 64 + s]  = base[(size_t)(64 + c) * SEQ + s0 + s];
            Vt[s * 65 + c]  = base[(size_t)(128 + c) * SEQ + s0 + s];
        }
        __syncthreads();

        // S = Q^T K (over c), scaled by 1/sqrt(dh) = 0.125
        float S[4][4] = {};
#pragma unroll 8
        for (int c = 0; c < 64; c++) {
            float4 q = *(float4*)&Qs[c * 64 + t4];
            float4 k = *(float4*)&KP[c * 64 + c4];
            S[0][0] += q.x * k.x; S[0][1] += q.x * k.y; S[0][2] += q.x * k.z; S[0][3] += q.x * k.w;
            S[1][0] += q.y * k.x; S[1][1] += q.y * k.y; S[1][2] += q.y * k.z; S[1][3] += q.y * k.w;
            S[2][0] += q.z * k.x; S[2][1] += q.z * k.y; S[2][2] += q.z * k.z; S[2][3] += q.z * k.w;
            S[3][0] += q.w * k.x; S[3][1] += q.w * k.y; S[3][2] += q.w * k.z; S[3][3] += q.w * k.w;
        }

        // online softmax (rows replicated across the 16 tx lanes of each ty)
#pragma unroll
        for (int i = 0; i < 4; i++) {
            float mx = S[i][0];
            mx = fmaxf(mx, S[i][1]); mx = fmaxf(mx, S[i][2]); mx = fmaxf(mx, S[i][3]);
            mx *= 0.125f;  // scale applied once (monotone; ok to scale before max too)
            // actually scale each element then reduce: redo properly below
            float s0v = S[i][0] * 0.125f, s1v = S[i][1] * 0.125f;
            float s2v = S[i][2] * 0.125f, s3v = S[i][3] * 0.125f;
            mx = fmaxf(fmaxf(s0v, s1v), fmaxf(s2v, s3v));
#pragma unroll
            for (int o = 8; o; o >>= 1)
                mx = fmaxf(mx, __shfl_xor_sync(0xffffffffu, mx, o, 16));
            const float mnew = fmaxf(m_run[i], mx);
            const float corr = __expf(m_run[i] - mnew);
            s0v = __expf(s0v - mnew); s1v = __expf(s1v - mnew);
            s2v = __expf(s2v - mnew); s3v = __expf(s3v - mnew);
            float rs = s0v + s1v + s2v + s3v;
#pragma unroll
            for (int o = 8; o; o >>= 1)
                rs += __shfl_xor_sync(0xffffffffu, rs, o, 16);
            l_run[i] = l_run[i] * corr + rs;
            m_run[i] = mnew;
            S[i][0] = s0v; S[i][1] = s1v; S[i][2] = s2v; S[i][3] = s3v;
#pragma unroll
            for (int j = 0; j < 4; j++) O[i][j] *= corr;
        }

        __syncthreads();  // all K reads done -> overwrite with P
#pragma unroll
        for (int i = 0; i < 4; i++)
            *(float4*)&KP[(t4 + i) * 64 + c4] =
                make_float4(S[i][0], S[i][1], S[i][2], S[i][3]);
        __syncthreads();

        // O[t][c] += sum_s P[t][s] * V[c][s]  (V transposed in smem)
#pragma unroll 4
        for (int s = 0; s < 64; s++) {
            const float p0 = KP[(t4 + 0) * 64 + s];
            const float p1 = KP[(t4 + 1) * 64 + s];
            const float p2 = KP[(t4 + 2) * 64 + s];
            const float p3 = KP[(t4 + 3) * 64 + s];
            const float v0 = Vt[s * 65 + c4 + 0];
            const float v1 = Vt[s * 65 + c4 + 1];
            const float v2 = Vt[s * 65 + c4 + 2];
            const float v3 = Vt[s * 65 + c4 + 3];
            O[0][0] += p0 * v0; O[0][1] += p0 * v1; O[0][2] += p0 * v2; O[0][3] += p0 * v3;
            O[1][0] += p1 * v0; O[1][1] += p1 * v1; O[1][2] += p1 * v2; O[1][3] += p1 * v3;
            O[2][0] += p2 * v0; O[2][1] += p2 * v1; O[2][2] += p2 * v2; O[2][3] += p2 * v3;
            O[3][0] += p3 * v0; O[3][1] += p3 * v1; O[3][2] += p3 * v2; O[3][3] += p3 * v3;
        }
    }

    // Epilogue: normalize and stage through smem as [c][t] for coalesced store
    float inv[4];
#pragma unroll
    for (int i = 0; i < 4; i++) inv[i] = 1.f / l_run[i];
    __syncthreads();
#pragma unroll
    for (int i = 0; i < 4; i++)
#pragma unroll
        for (int j = 0; j < 4; j++)
            KP[(c4 + j) * 64 + (t4 + i)] = O[i][j] * inv[i];
    __syncthreads();
    for (int idx = tid; idx < 64 * 64; idx += 256) {
        const int c = idx >> 6, t = idx & 63;
        ao[((size_t)b * CH + (size_t)hh * 64 + c) * SEQ + t0 + t] = KP[c * 64 + t];
    }
}

// Final: out[b, o] = x[b, o, 0]
__global__ void extract_col0(const float* __restrict__ x, float* __restrict__ out)
{
    const int i = blockIdx.x * 256 + threadIdx.x;
    if (i < BATCH * CH) out[i] = x[(size_t)i * SEQ];
}

extern "C" void kernel_launch(void* const* d_in, const int* in_sizes, int n_in,
                              void* d_out, int out_size)
{
    const float* speech = (const float*)d_in[0];
    const float* init_w = (const float*)d_in[1];
    const float* init_b = (const float*)d_in[2];
    const float* gn_w   = (const float*)d_in[3];
    const float* gn_b   = (const float*)d_in[4];
    const float* qkv_w  = (const float*)d_in[5];
    const float* qkv_b  = (const float*)d_in[6];
    const float* proj_w = (const float*)d_in[7];
    const float* proj_b = (const float*)d_in[8];
    float* out = (float*)d_out;

    float *px, *ph, *pqkv, *pao;
    cudaGetSymbolAddress((void**)&px,   g_x);
    cudaGetSymbolAddress((void**)&ph,   g_h);
    cudaGetSymbolAddress((void**)&pqkv, g_qkv);
    cudaGetSymbolAddress((void**)&pao,  g_ao);

    const int ATTN_SMEM = (2 * 64 * 64 + 64 * 65) * sizeof(float);  // 49408
    cudaFuncSetAttribute(attn, cudaFuncAttributeMaxDynamicSharedMemorySize, ATTN_SMEM);

    // init projection: x = init_w @ speech + init_b
    gemm_bias_res<<<dim3(16, 16, 8), 256>>>(init_w, speech, init_b, nullptr,
                                            px, CH, SEQ, SPECD);

    for (int l = 0; l < LAYERS; l++) {
        groupnorm<<<256, 256>>>(px, gn_w + l * CH, gn_b + l * CH, ph);
        gemm_bias_res<<<dim3(16, 48, 8), 256>>>(
            qkv_w + (size_t)l * 3 * CH * CH, ph, qkv_b + (size_t)l * 3 * CH,
            nullptr, pqkv, 3 * CH, SEQ, CH);
        attn<<<dim3(16, 128), 256, ATTN_SMEM>>>(pqkv, pao);
        gemm_bias_res<<<dim3(16, 16, 8), 256>>>(
            proj_w + (size_t)l * CH * CH, pao, proj_b + (size_t)l * CH,
            px, px, CH, SEQ, CH);
    }

    extract_col0<<<32, 256>>>(px, out);
}

// round 5
// speedup vs baseline: 2.9143x; 2.9143x over previous
#include <cuda_runtime.h>
#include <cstdint>
#include <math.h>

#define BATCH 8
#define CH 1024
#define SEQ 1024
#define HEADS 16
#define DHEAD 64
#define GROUPS 32
#define CPG (CH / GROUPS)
#define LAYERS 6
#define SPECD 80

// Scratch (device globals: allowed, no runtime allocation)
__device__ float g_x[BATCH * CH * SEQ];        // residual stream
__device__ float g_h[BATCH * CH * SEQ];        // groupnorm output
__device__ float g_qkv[BATCH * 3 * CH * SEQ];  // qkv activations
__device__ float g_ao[BATCH * CH * SEQ];       // attention output
__device__ float g_q0[BATCH * CH];             // last-layer q at t=0
__device__ float g_o0[BATCH * CH];             // last-layer attn out at t=0

// ---------------------------------------------------------------------------
// helpers
// ---------------------------------------------------------------------------
__device__ __forceinline__ float to_tf32(float x) {
    unsigned u;
    asm("cvt.rna.tf32.f32 %0, %1;" : "=r"(u) : "f"(x));
    return __uint_as_float(u);
}

// D(16x8) += A(16x8,row) * B(8x8,col) ; tf32 in, fp32 acc
__device__ __forceinline__ void mma_tf32(float* d, const float* a, const float* b) {
    asm volatile(
        "mma.sync.aligned.m16n8k8.row.col.f32.tf32.tf32.f32 "
        "{%0,%1,%2,%3}, {%4,%5,%6,%7}, {%8,%9}, {%0,%1,%2,%3};\n"
        : "+f"(d[0]), "+f"(d[1]), "+f"(d[2]), "+f"(d[3])
        : "r"(__float_as_uint(a[0])), "r"(__float_as_uint(a[1])),
          "r"(__float_as_uint(a[2])), "r"(__float_as_uint(a[3])),
          "r"(__float_as_uint(b[0])), "r"(__float_as_uint(b[1])));
}

// ---------------------------------------------------------------------------
// tf32 GEMM: out[b,gr(m),n] = bias[gr(m)] + (res? res[...]) + sum_k W[gr(m),k] X[b,k,n]
// gr(m) = m when head_remap==0;
// gr(m) = (m>>7)*192 + 64 + (m&127) when head_remap==1  (per-head k/v block).
// W: rows indexed by gr(m), K cols. X: per-batch KxN row-major.
// Block 128x128, kc=16, 8 warps (64x32 warp tile). M%128==0, N%128==0, K%16==0.
// ---------------------------------------------------------------------------
#define AS_ST 20
#define BS_ST 132
__global__ __launch_bounds__(256) void gemm_tf32(
    const float* __restrict__ W, const float* __restrict__ X,
    const float* __restrict__ bias, const float* __restrict__ res,
    float* __restrict__ out, int M, int N, int K, size_t out_bstride,
    int head_remap)
{
    __shared__ __align__(16) float As[2][128 * AS_ST];
    __shared__ __align__(16) float Bs[2][16 * BS_ST];

    const int b  = blockIdx.z;
    const int m0 = blockIdx.y * 128;
    const int n0 = blockIdx.x * 128;
    const float* Xb = X + (size_t)b * K * N;

    const int tid  = threadIdx.x;
    const int lane = tid & 31;
    const int wid  = tid >> 5;
    const int wm   = wid & 1;
    const int wn   = wid >> 1;
    const int lg   = lane >> 2;   // group id (row)
    const int lt   = lane & 3;    // thread in group (k / col pair)

    // gmem load mapping
    const int a_row = tid >> 1;           // 0..127
    const int a_kb  = (tid & 1) * 8;      // 0 or 8
    const int b_row = tid >> 4;           // 0..15
    const int b_nb  = (tid & 15) * 8;     // 0..120

    // global row for the W-load row of this thread
    const int a_grow = head_remap ? ((m0 >> 7) * 192 + 64 + a_row) : (m0 + a_row);

    float acc[4][4][4];
#pragma unroll
    for (int i = 0; i < 4; i++)
#pragma unroll
        for (int j = 0; j < 4; j++)
#pragma unroll
            for (int r = 0; r < 4; r++) acc[i][j][r] = 0.f;

    // prologue: load k-stage 0
    {
        const float* wp = W + (size_t)a_grow * K + a_kb;
        float4 w0 = *(const float4*)(wp);
        float4 w1 = *(const float4*)(wp + 4);
        float* as = &As[0][a_row * AS_ST + a_kb];
        as[0] = to_tf32(w0.x); as[1] = to_tf32(w0.y); as[2] = to_tf32(w0.z); as[3] = to_tf32(w0.w);
        as[4] = to_tf32(w1.x); as[5] = to_tf32(w1.y); as[6] = to_tf32(w1.z); as[7] = to_tf32(w1.w);
        const float* xp = Xb + (size_t)b_row * N + n0 + b_nb;
        float4 x0 = *(const float4*)(xp);
        float4 x1 = *(const float4*)(xp + 4);
        float* bs = &Bs[0][b_row * BS_ST + b_nb];
        bs[0] = to_tf32(x0.x); bs[1] = to_tf32(x0.y); bs[2] = to_tf32(x0.z); bs[3] = to_tf32(x0.w);
        bs[4] = to_tf32(x1.x); bs[5] = to_tf32(x1.y); bs[6] = to_tf32(x1.z); bs[7] = to_tf32(x1.w);
    }
    __syncthreads();

    int buf = 0;
    for (int k0 = 0; k0 < K; k0 += 16) {
        float4 w0, w1, x0, x1;
        const bool more = (k0 + 16) < K;
        if (more) {
            const float* wp = W + (size_t)a_grow * K + k0 + 16 + a_kb;
            w0 = *(const float4*)(wp);
            w1 = *(const float4*)(wp + 4);
            const float* xp = Xb + (size_t)(k0 + 16 + b_row) * N + n0 + b_nb;
            x0 = *(const float4*)(xp);
            x1 = *(const float4*)(xp + 4);
        }

        const float* as = As[buf];
        const float* bs = Bs[buf];
#pragma unroll
        for (int kk = 0; kk < 16; kk += 8) {
            float a[4][4], bb[4][2];
#pragma unroll
            for (int mt = 0; mt < 4; mt++) {
                const int r = wm * 64 + mt * 16 + lg;
                a[mt][0] = as[r * AS_ST + kk + lt];
                a[mt][1] = as[(r + 8) * AS_ST + kk + lt];
                a[mt][2] = as[r * AS_ST + kk + 4 + lt];
                a[mt][3] = as[(r + 8) * AS_ST + kk + 4 + lt];
            }
#pragma unroll
            for (int nt = 0; nt < 4; nt++) {
                const int c = wn * 32 + nt * 8 + lg;
                bb[nt][0] = bs[(kk + lt) * BS_ST + c];
                bb[nt][1] = bs[(kk + 4 + lt) * BS_ST + c];
            }
#pragma unroll
            for (int mt = 0; mt < 4; mt++)
#pragma unroll
                for (int nt = 0; nt < 4; nt++)
                    mma_tf32(acc[mt][nt], a[mt], bb[nt]);
        }

        if (more) {
            float* asn = &As[buf ^ 1][a_row * AS_ST + a_kb];
            asn[0] = to_tf32(w0.x); asn[1] = to_tf32(w0.y); asn[2] = to_tf32(w0.z); asn[3] = to_tf32(w0.w);
            asn[4] = to_tf32(w1.x); asn[5] = to_tf32(w1.y); asn[6] = to_tf32(w1.z); asn[7] = to_tf32(w1.w);
            float* bsn = &Bs[buf ^ 1][b_row * BS_ST + b_nb];
            bsn[0] = to_tf32(x0.x); bsn[1] = to_tf32(x0.y); bsn[2] = to_tf32(x0.z); bsn[3] = to_tf32(x0.w);
            bsn[4] = to_tf32(x1.x); bsn[5] = to_tf32(x1.y); bsn[6] = to_tf32(x1.z); bsn[7] = to_tf32(x1.w);
        }
        __syncthreads();
        buf ^= 1;
    }

    // epilogue
    const size_t ob = (size_t)b * out_bstride;
#pragma unroll
    for (int mt = 0; mt < 4; mt++) {
        const int ml = m0 + wm * 64 + mt * 16 + lg;   // logical row
        const int r0 = head_remap ? ((ml >> 7) * 192 + 64 + (ml & 127)) : ml;
        const float bi0 = bias[r0];
        const float bi1 = bias[r0 + 8];
#pragma unroll
        for (int nt = 0; nt < 4; nt++) {
            const int c = n0 + wn * 32 + nt * 8 + 2 * lt;
            float2 v0 = make_float2(acc[mt][nt][0] + bi0, acc[mt][nt][1] + bi0);
            float2 v1 = make_float2(acc[mt][nt][2] + bi1, acc[mt][nt][3] + bi1);
            const size_t o0 = ob + (size_t)r0 * N + c;
            const size_t o1 = ob + (size_t)(r0 + 8) * N + c;
            if (res) {
                float2 r0v = *(const float2*)(res + o0);
                float2 r1v = *(const float2*)(res + o1);
                v0.x += r0v.x; v0.y += r0v.y; v1.x += r1v.x; v1.y += r1v.y;
            }
            *(float2*)(out + o0) = v0;
            *(float2*)(out + o1) = v1;
        }
    }
}

// ---------------------------------------------------------------------------
// GroupNorm: one block per (batch, group).
// ---------------------------------------------------------------------------
__global__ __launch_bounds__(256) void groupnorm(
    const float* __restrict__ x, const float* __restrict__ w,
    const float* __restrict__ bb, float* __restrict__ h)
{
    const int bg = blockIdx.x;
    const int b  = bg >> 5;
    const int g  = bg & 31;
    const size_t off = (size_t)b * CH * SEQ + (size_t)g * CPG * SEQ;
    const float* xp = x + off;
    float* hp = h + off;
    const int n = CPG * SEQ;

    float s = 0.f, s2 = 0.f;
    for (int i = threadIdx.x * 4; i < n; i += 1024) {
        float4 v = *(const float4*)(xp + i);
        s  += v.x + v.y + v.z + v.w;
        s2 += v.x * v.x + v.y * v.y + v.z * v.z + v.w * v.w;
    }
#pragma unroll
    for (int o = 16; o; o >>= 1) {
        s  += __shfl_xor_sync(0xffffffffu, s,  o);
        s2 += __shfl_xor_sync(0xffffffffu, s2, o);
    }
    __shared__ float ws[8], ws2[8];
    const int wi = threadIdx.x >> 5, li = threadIdx.x & 31;
    if (li == 0) { ws[wi] = s; ws2[wi] = s2; }
    __syncthreads();
    if (threadIdx.x == 0) {
        float S = 0.f, S2 = 0.f;
#pragma unroll
        for (int k = 0; k < 8; k++) { S += ws[k]; S2 += ws2[k]; }
        const float mean = S / n;
        const float var  = S2 / n - mean * mean;
        ws[0]  = mean;
        ws2[0] = rsqrtf(var + 1e-5f);
    }
    __syncthreads();
    const float mean = ws[0], rstd = ws2[0];
    for (int i = threadIdx.x * 4; i < n; i += 1024) {
        const int c = g * CPG + (i >> 10);
        const float sc = rstd * w[c];
        const float sb = bb[c] - mean * sc;
        float4 v = *(const float4*)(xp + i);
        v.x = v.x * sc + sb; v.y = v.y * sc + sb;
        v.z = v.z * sc + sb; v.w = v.w * sc + sb;
        *(float4*)(hp + i) = v;
    }
}

// ---------------------------------------------------------------------------
// tf32 flash attention. Block = (b,h) x 128-query tile; 8 warps x 16 rows.
// qkv: [B, 3*CH, SEQ]; head h rows [h*192, +192): q/k/v each 64 rows.
// smem (floats): Qs[64][132] | Ks[64][68] | Vs[64][68] | Ps[128][68]
// ---------------------------------------------------------------------------
#define Q_ST 132
#define K_ST 68
__global__ __launch_bounds__(256) void attn_tf32(
    const float* __restrict__ qkv, float* __restrict__ ao)
{
    extern __shared__ float sm[];
    float* Qs = sm;                  // 8448
    float* Ks = sm + 8448;           // 4352
    float* Vs = sm + 12800;          // 4352
    float* Ps = sm + 17152;          // 8704  (total 25856 floats)

    const int bh = blockIdx.y;
    const int b  = bh >> 4;
    const int hh = bh & 15;
    const int t0 = blockIdx.x * 128;
    const float* base = qkv + ((size_t)b * 3 * CH + (size_t)hh * 192) * SEQ;

    const int tid  = threadIdx.x;
    const int lane = tid & 31;
    const int wid  = tid >> 5;
    const int lg   = lane >> 2;
    const int lt   = lane & 3;
    const int tr0  = wid * 16;       // warp's local query rows [tr0, tr0+16)

    // Load Q tile (tf32-converted): Qs[c][t]
#pragma unroll
    for (int j = 0; j < 8; j++) {
        const int lin = tid + j * 256;      // f4 index over 64x32
        const int c  = lin >> 5;
        const int tp = (lin & 31) * 4;
        float4 v = *(const float4*)(base + (size_t)c * SEQ + t0 + tp);
        v.x = to_tf32(v.x); v.y = to_tf32(v.y); v.z = to_tf32(v.z); v.w = to_tf32(v.w);
        *(float4*)&Qs[c * Q_ST + tp] = v;
    }

    float O[8][4];
#pragma unroll
    for (int nt = 0; nt < 8; nt++)
#pragma unroll
        for (int r = 0; r < 4; r++) O[nt][r] = 0.f;
    float m0 = -1e30f, m1 = -1e30f, l0 = 0.f, l1 = 0.f;

    for (int st = 0; st < SEQ / 64; st++) {
        const int s0 = st * 64;
        __syncthreads();   // previous iteration's V reads complete
#pragma unroll
        for (int j = 0; j < 4; j++) {
            const int lin = tid + j * 256;  // f4 index over 64x16
            const int c  = lin >> 4;
            const int sp = (lin & 15) * 4;
            float4 k = *(const float4*)(base + (size_t)(64 + c) * SEQ + s0 + sp);
            float4 v = *(const float4*)(base + (size_t)(128 + c) * SEQ + s0 + sp);
            k.x = to_tf32(k.x); k.y = to_tf32(k.y); k.z = to_tf32(k.z); k.w = to_tf32(k.w);
            v.x = to_tf32(v.x); v.y = to_tf32(v.y); v.z = to_tf32(v.z); v.w = to_tf32(v.w);
            *(float4*)&Ks[c * K_ST + sp] = k;
            *(float4*)&Vs[c * K_ST + sp] = v;
        }
        __syncthreads();

        // S = Q^T K  (A[t][c] = Qs[c][t], B[c][s] = Ks[c][s])
        float S[8][4];
#pragma unroll
        for (int nt = 0; nt < 8; nt++)
#pragma unroll
            for (int r = 0; r < 4; r++) S[nt][r] = 0.f;
#pragma unroll
        for (int kk = 0; kk < 64; kk += 8) {
            float a[4];
            a[0] = Qs[(kk + lt) * Q_ST + tr0 + lg];
            a[1] = Qs[(kk + lt) * Q_ST + tr0 + 8 + lg];
            a[2] = Qs[(kk + 4 + lt) * Q_ST + tr0 + lg];
            a[3] = Qs[(kk + 4 + lt) * Q_ST + tr0 + 8 + lg];
#pragma unroll
            for (int nt = 0; nt < 8; nt++) {
                float bb[2];
                bb[0] = Ks[(kk + lt) * K_ST + nt * 8 + lg];
                bb[1] = Ks[(kk + 4 + lt) * K_ST + nt * 8 + lg];
                mma_tf32(S[nt], a, bb);
            }
        }

        // online softmax (rows r=lane>>2 and r+8 of this warp tile)
        float mx0 = -1e30f, mx1 = -1e30f;
#pragma unroll
        for (int nt = 0; nt < 8; nt++) {
            S[nt][0] *= 0.125f; S[nt][1] *= 0.125f;
            S[nt][2] *= 0.125f; S[nt][3] *= 0.125f;
            mx0 = fmaxf(mx0, fmaxf(S[nt][0], S[nt][1]));
            mx1 = fmaxf(mx1, fmaxf(S[nt][2], S[nt][3]));
        }
#pragma unroll
        for (int o = 1; o < 4; o <<= 1) {
            mx0 = fmaxf(mx0, __shfl_xor_sync(0xffffffffu, mx0, o, 4));
            mx1 = fmaxf(mx1, __shfl_xor_sync(0xffffffffu, mx1, o, 4));
        }
        const float mn0 = fmaxf(m0, mx0);
        const float mn1 = fmaxf(m1, mx1);
        const float cr0 = __expf(m0 - mn0);
        const float cr1 = __expf(m1 - mn1);
        float sum0 = 0.f, sum1 = 0.f;
#pragma unroll
        for (int nt = 0; nt < 8; nt++) {
            S[nt][0] = __expf(S[nt][0] - mn0);
            S[nt][1] = __expf(S[nt][1] - mn0);
            S[nt][2] = __expf(S[nt][2] - mn1);
            S[nt][3] = __expf(S[nt][3] - mn1);
            sum0 += S[nt][0] + S[nt][1];
            sum1 += S[nt][2] + S[nt][3];
        }
#pragma unroll
        for (int o = 1; o < 4; o <<= 1) {
            sum0 += __shfl_xor_sync(0xffffffffu, sum0, o, 4);
            sum1 += __shfl_xor_sync(0xffffffffu, sum1, o, 4);
        }
        l0 = l0 * cr0 + sum0;
        l1 = l1 * cr1 + sum1;
        m0 = mn0; m1 = mn1;
#pragma unroll
        for (int nt = 0; nt < 8; nt++) {
            O[nt][0] *= cr0; O[nt][1] *= cr0;
            O[nt][2] *= cr1; O[nt][3] *= cr1;
        }

        // stage P (warp-private rows) as tf32
        __syncwarp();
#pragma unroll
        for (int nt = 0; nt < 8; nt++) {
            const int col = nt * 8 + 2 * lt;
            *(float2*)&Ps[(tr0 + lg) * K_ST + col] =
                make_float2(to_tf32(S[nt][0]), to_tf32(S[nt][1]));
            *(float2*)&Ps[(tr0 + 8 + lg) * K_ST + col] =
                make_float2(to_tf32(S[nt][2]), to_tf32(S[nt][3]));
        }
        __syncwarp();

        // O += P * V^T  (A[t][s] = Ps, B[s][c] = Vs[c][s])
#pragma unroll
        for (int kk = 0; kk < 64; kk += 8) {
            float a[4];
            a[0] = Ps[(tr0 + lg) * K_ST + kk + lt];
            a[1] = Ps[(tr0 + 8 + lg) * K_ST + kk + lt];
            a[2] = Ps[(tr0 + lg) * K_ST + kk + 4 + lt];
            a[3] = Ps[(tr0 + 8 + lg) * K_ST + kk + 4 + lt];
#pragma unroll
            for (int nt = 0; nt < 8; nt++) {
                float bb[2];
                bb[0] = Vs[(nt * 8 + lg) * K_ST + kk + lt];
                bb[1] = Vs[(nt * 8 + lg) * K_ST + kk + 4 + lt];
                mma_tf32(O[nt], a, bb);
            }
        }
    }

    // normalize + transpose through Qs (reused) for coalesced store
    const float inv0 = 1.f / l0;
    const float inv1 = 1.f / l1;
    __syncthreads();   // everyone done with Q reads
#pragma unroll
    for (int nt = 0; nt < 8; nt++) {
        const int col = nt * 8 + 2 * lt;
        Qs[(col) * Q_ST + tr0 + lg]         = O[nt][0] * inv0;
        Qs[(col + 1) * Q_ST + tr0 + lg]     = O[nt][1] * inv0;
        Qs[(col) * Q_ST + tr0 + 8 + lg]     = O[nt][2] * inv1;
        Qs[(col + 1) * Q_ST + tr0 + 8 + lg] = O[nt][3] * inv1;
    }
    __syncthreads();
#pragma unroll
    for (int j = 0; j < 8; j++) {
        const int lin = tid + j * 256;
        const int c  = lin >> 5;
        const int tp = (lin & 31) * 4;
        *(float4*)(ao + ((size_t)b * CH + (size_t)hh * 64 + c) * SEQ + t0 + tp) =
            *(float4*)&Qs[c * Q_ST + tp];
    }
}

// ---------------------------------------------------------------------------
// Last layer specializations (only column t=0 of the output is consumed)
// q0[b, h*64+j] = qkv_b[h*192+j] + sum_k qkv_w[h*192+j, k] * h[b,k,0]
// ---------------------------------------------------------------------------
__global__ __launch_bounds__(256) void gemv_q0(
    const float* __restrict__ W, const float* __restrict__ h,
    const float* __restrict__ bias, float* __restrict__ q0)
{
    const int gw = blockIdx.x * 8 + (threadIdx.x >> 5);
    const int lane = threadIdx.x & 31;
    const int b = gw >> 10;
    const int m = gw & 1023;                       // h*64 + j
    const int row = (m >> 6) * 192 + (m & 63);     // global q row
    float s = 0.f;
    for (int k = lane; k < CH; k += 32)
        s += W[(size_t)row * CH + k] * h[((size_t)b * CH + k) * SEQ];
#pragma unroll
    for (int o = 16; o; o >>= 1) s += __shfl_xor_sync(0xffffffffu, s, o);
    if (lane == 0) q0[b * CH + m] = s + bias[row];
}

// single-query attention: block = (b,h); o0[b, h*64+c]
__global__ __launch_bounds__(256) void attn_last(
    const float* __restrict__ qkv, const float* __restrict__ q0,
    float* __restrict__ o0)
{
    __shared__ float q[64];
    __shared__ float lgt[SEQ];
    __shared__ float red[256];
    __shared__ float s_m, s_l;

    const int b  = blockIdx.x >> 4;
    const int hh = blockIdx.x & 15;
    const int tid = threadIdx.x;
    const float* base = qkv + ((size_t)b * 3 * CH + (size_t)hh * 192) * SEQ;

    if (tid < 64) q[tid] = q0[b * CH + hh * 64 + tid];
    __syncthreads();

    // logits
#pragma unroll
    for (int j = 0; j < 4; j++) {
        const int s = tid + j * 256;
        float acc = 0.f;
#pragma unroll 8
        for (int c = 0; c < 64; c++)
            acc += q[c] * base[(size_t)(64 + c) * SEQ + s];
        lgt[s] = acc * 0.125f;
    }
    __syncthreads();

    // max
    float mx = -1e30f;
#pragma unroll
    for (int j = 0; j < 4; j++) mx = fmaxf(mx, lgt[tid + j * 256]);
    red[tid] = mx;
    __syncthreads();
    for (int stp = 128; stp; stp >>= 1) {
        if (tid < stp) red[tid] = fmaxf(red[tid], red[tid + stp]);
        __syncthreads();
    }
    if (tid == 0) s_m = red[0];
    __syncthreads();
    const float mxv = s_m;

    // exp + sum
    float sum = 0.f;
#pragma unroll
    for (int j = 0; j < 4; j++) {
        const int s = tid + j * 256;
        const float p = __expf(lgt[s] - mxv);
        lgt[s] = p;
        sum += p;
    }
    __syncthreads();
    red[tid] = sum;
    __syncthreads();
    for (int stp = 128; stp; stp >>= 1) {
        if (tid < stp) red[tid] += red[tid + stp];
        __syncthreads();
    }
    if (tid == 0) s_l = red[0];
    __syncthreads();

    // o[c] = sum_s p[s] v[c,s]
    const int c  = tid >> 2;
    const int si = tid & 3;
    float part = 0.f;
    const float* vrow = base + (size_t)(128 + c) * SEQ;
    for (int s = si * 256; s < si * 256 + 256; s++) part += lgt[s] * vrow[s];
    red[tid] = part;
    __syncthreads();
    if (tid < 64) {
        const float o = (red[tid * 4] + red[tid * 4 + 1] +
                         red[tid * 4 + 2] + red[tid * 4 + 3]) / s_l;
        o0[b * CH + hh * 64 + tid] = o;
    }
}

// out[b,m] = x[b,m,0] + proj_b[m] + sum_k proj_w[m,k] * o0[b,k]
__global__ __launch_bounds__(256) void proj_last(
    const float* __restrict__ W, const float* __restrict__ o0,
    const float* __restrict__ bias, const float* __restrict__ x,
    float* __restrict__ out)
{
    const int gw = blockIdx.x * 8 + (threadIdx.x >> 5);
    const int lane = threadIdx.x & 31;
    const int b = gw >> 10;
    const int m = gw & 1023;
    float s = 0.f;
    for (int k = lane; k < CH; k += 32)
        s += W[(size_t)m * CH + k] * o0[b * CH + k];
#pragma unroll
    for (int o = 16; o; o >>= 1) s += __shfl_xor_sync(0xffffffffu, s, o);
    if (lane == 0)
        out[b * CH + m] = s + bias[m] + x[((size_t)b * CH + m) * SEQ];
}

// ---------------------------------------------------------------------------
extern "C" void kernel_launch(void* const* d_in, const int* in_sizes, int n_in,
                              void* d_out, int out_size)
{
    const float* speech = (const float*)d_in[0];
    const float* init_w = (const float*)d_in[1];
    const float* init_b = (const float*)d_in[2];
    const float* gn_w   = (const float*)d_in[3];
    const float* gn_b   = (const float*)d_in[4];
    const float* qkv_w  = (const float*)d_in[5];
    const float* qkv_b  = (const float*)d_in[6];
    const float* proj_w = (const float*)d_in[7];
    const float* proj_b = (const float*)d_in[8];
    float* out = (float*)d_out;

    float *px, *ph, *pqkv, *pao, *pq0, *po0;
    cudaGetSymbolAddress((void**)&px,   g_x);
    cudaGetSymbolAddress((void**)&ph,   g_h);
    cudaGetSymbolAddress((void**)&pqkv, g_qkv);
    cudaGetSymbolAddress((void**)&pao,  g_ao);
    cudaGetSymbolAddress((void**)&pq0,  g_q0);
    cudaGetSymbolAddress((void**)&po0,  g_o0);

    const int ATTN_SMEM = 25856 * sizeof(float);  // 103424 B
    cudaFuncSetAttribute(attn_tf32, cudaFuncAttributeMaxDynamicSharedMemorySize, ATTN_SMEM);

    // init projection: x = init_w @ speech + init_b   (M=1024, N=1024, K=80)
    gemm_tf32<<<dim3(8, 8, 8), 256>>>(init_w, speech, init_b, nullptr,
                                      px, CH, SEQ, SPECD, (size_t)CH * SEQ, 0);

    for (int l = 0; l < LAYERS - 1; l++) {
        groupnorm<<<256, 256>>>(px, gn_w + l * CH, gn_b + l * CH, ph);
        gemm_tf32<<<dim3(8, 24, 8), 256>>>(
            qkv_w + (size_t)l * 3 * CH * CH, ph, qkv_b + (size_t)l * 3 * CH,
            nullptr, pqkv, 3 * CH, SEQ, CH, (size_t)3 * CH * SEQ, 0);
        attn_tf32<<<dim3(8, 128), 256, ATTN_SMEM>>>(pqkv, pao);
        gemm_tf32<<<dim3(8, 8, 8), 256>>>(
            proj_w + (size_t)l * CH * CH, pao, proj_b + (size_t)l * CH,
            px, px, CH, SEQ, CH, (size_t)CH * SEQ, 0);
    }

    // last layer: only t=0 output needed
    {
        const int l = LAYERS - 1;
        groupnorm<<<256, 256>>>(px, gn_w + l * CH, gn_b + l * CH, ph);
        // k,v rows of every head: logical M=2048; block by==head h maps to
        // global rows h*192+64 .. h*192+191 (head_remap=1).
        gemm_tf32<<<dim3(8, 16, 8), 256>>>(
            qkv_w + (size_t)l * 3 * CH * CH, ph,
            qkv_b + (size_t)l * 3 * CH, nullptr,
            pqkv, 2 * CH, SEQ, CH, (size_t)3 * CH * SEQ, 1);
        // q at t=0 only (q rows h*192+[0,64))
        gemv_q0<<<1024, 256>>>(qkv_w + (size_t)l * 3 * CH * CH, ph,
                               qkv_b + (size_t)l * 3 * CH, pq0);
        attn_last<<<128, 256>>>(pqkv, pq0, po0);
        proj_last<<<1024, 256>>>(proj_w + (size_t)l * CH * CH, po0,
                                 proj_b + (size_t)l * CH, px, out);
    }
}